// round 15
// baseline (speedup 1.0000x reference)
#include <cuda_runtime.h>
#include <math.h>
#include <stdint.h>

typedef unsigned long long ull;

// Scratch: projected inputs [t][b][768] (xz cols 0..511 incl bias, xh cols 512..767)
__device__ float g_xzh[131072 * 768];  // 402 MB static scratch

// ---------------------------------------------------------------------------
// helpers
// ---------------------------------------------------------------------------
__device__ __forceinline__ ull dup2f(float x) {
    ull r; asm("mov.b64 %0, {%1, %1};" : "=l"(r) : "f"(x)); return r;
}
__device__ __forceinline__ void unpack2(ull v, float& x, float& y) {
    asm("mov.b64 {%0, %1}, %2;" : "=f"(x), "=f"(y) : "l"(v));
}
__device__ __forceinline__ void ffma2(ull& d, ull a, ull b) {
    asm("fma.rn.f32x2 %0, %1, %2, %0;" : "+l"(d) : "l"(a), "l"(b));
}
__device__ __forceinline__ uint32_t smem_u32(const void* p) {
    return (uint32_t)__cvta_generic_to_shared(p);
}
__device__ __forceinline__ uint32_t mapa_rank(uint32_t addr, uint32_t rank) {
    uint32_t r; asm("mapa.shared::cluster.u32 %0, %1, %2;" : "=r"(r) : "r"(addr), "r"(rank));
    return r;
}
__device__ __forceinline__ void st_cluster_f4(uint32_t addr, float4 v) {
    asm volatile("st.shared::cluster.v4.f32 [%0], {%1,%2,%3,%4};"
                 :: "r"(addr), "f"(v.x), "f"(v.y), "f"(v.z), "f"(v.w) : "memory");
}
__device__ __forceinline__ void cluster_sync_() {
    asm volatile("barrier.cluster.arrive.aligned;" ::: "memory");
    asm volatile("barrier.cluster.wait.aligned;" ::: "memory");
}
__device__ __forceinline__ float sigf(float x) {
    return __fdividef(1.f, 1.f + __expf(-x));
}
__device__ __forceinline__ float tanhfast(float x) {
    float a = fabsf(x);
    float e = __expf(2.f * a);
    float r = 1.f - __fdividef(2.f, e + 1.f);
    return copysignf(r, x);
}

// ---------------------------------------------------------------------------
// Kernel 1: projection GEMM, double-buffered (measured ~1.13 ms, kept as-is).
// ---------------------------------------------------------------------------
__global__ __launch_bounds__(256, 2) void proj_gemm(
    const float* __restrict__ x,
    const float* __restrict__ Wzr,
    const float* __restrict__ Wh,
    const float* __restrict__ bzr,
    const float* __restrict__ bh)
{
    __shared__ float As[2][128][16];
    __shared__ float Bs[2][16][128];

    const int tid = threadIdx.x;
    const int tm = tid >> 4;
    const int tn = tid & 15;
    const int Mbase = blockIdx.y * 128;
    const int Nbase = blockIdx.x * 128;

    const bool isZr = (Nbase < 512);
    const float* __restrict__ W = isZr ? Wzr : Wh;
    const int ldw  = isZr ? 512 : 256;
    const int wcol = isZr ? Nbase : (Nbase - 512);

    ull acc2[8][4];
    #pragma unroll
    for (int i = 0; i < 8; i++)
        #pragma unroll
        for (int p = 0; p < 4; p++) acc2[i][p] = 0ull;

    const int ra = tid >> 2;
    const int ka = (tid & 3) << 2;
    const int rb = tid >> 5;
    const int nb = (tid & 31) << 2;

    float4 a0 = *(const float4*)&x[(size_t)(Mbase + ra)      * 256 + ka];
    float4 a1 = *(const float4*)&x[(size_t)(Mbase + ra + 64) * 256 + ka];
    float4 w0 = *(const float4*)&W[(size_t)(rb)     * ldw + wcol + nb];
    float4 w1 = *(const float4*)&W[(size_t)(rb + 8) * ldw + wcol + nb];
    *(float4*)&As[0][ra][ka]      = a0;
    *(float4*)&As[0][ra + 64][ka] = a1;
    *(float4*)&Bs[0][rb][nb]      = w0;
    *(float4*)&Bs[0][rb + 8][nb]  = w1;
    __syncthreads();

    int cur = 0;
    for (int kt = 16; kt <= 256; kt += 16) {
        if (kt < 256) {
            a0 = *(const float4*)&x[(size_t)(Mbase + ra)      * 256 + kt + ka];
            a1 = *(const float4*)&x[(size_t)(Mbase + ra + 64) * 256 + kt + ka];
            w0 = *(const float4*)&W[(size_t)(kt + rb)     * ldw + wcol + nb];
            w1 = *(const float4*)&W[(size_t)(kt + rb + 8) * ldw + wcol + nb];
        }
        #pragma unroll
        for (int kk = 0; kk < 16; kk++) {
            ulonglong2 b01 = *(const ulonglong2*)&Bs[cur][kk][tn * 8];
            ulonglong2 b23 = *(const ulonglong2*)&Bs[cur][kk][tn * 8 + 4];
            #pragma unroll
            for (int i = 0; i < 8; i++) {
                ull ad = dup2f(As[cur][tm * 8 + i][kk]);
                ffma2(acc2[i][0], ad, b01.x);
                ffma2(acc2[i][1], ad, b01.y);
                ffma2(acc2[i][2], ad, b23.x);
                ffma2(acc2[i][3], ad, b23.y);
            }
        }
        if (kt < 256) {
            int nxt = cur ^ 1;
            *(float4*)&As[nxt][ra][ka]      = a0;
            *(float4*)&As[nxt][ra + 64][ka] = a1;
            *(float4*)&Bs[nxt][rb][nb]      = w0;
            *(float4*)&Bs[nxt][rb + 8][nb]  = w1;
            __syncthreads();
            cur = nxt;
        }
    }

    float bias[8];
    #pragma unroll
    for (int jj = 0; jj < 8; jj++) {
        int c = Nbase + tn * 8 + jj;
        bias[jj] = (c < 512) ? bzr[c] : bh[c - 512];
    }

    #pragma unroll
    for (int i = 0; i < 8; i++) {
        int r = Mbase + tm * 8 + i;   // r = b*1024 + t
        int b = r >> 10;
        int t = r & 1023;
        float* dst = &g_xzh[(size_t)((t << 7) + b) * 768 + Nbase + tn * 8];
        float c[8];
        #pragma unroll
        for (int p = 0; p < 4; p++) unpack2(acc2[i][p], c[2 * p], c[2 * p + 1]);
        float4 v0, v1;
        v0.x = c[0] + bias[0]; v0.y = c[1] + bias[1];
        v0.z = c[2] + bias[2]; v0.w = c[3] + bias[3];
        v1.x = c[4] + bias[4]; v1.y = c[5] + bias[5];
        v1.z = c[6] + bias[6]; v1.w = c[7] + bias[7];
        *(float4*)dst       = v0;
        *(float4*)(dst + 4) = v1;
    }
}

// ---------------------------------------------------------------------------
// Kernel 2: GRU recurrence — EXACT R9 skeleton (best measured: 2437 us) with
// ONE change: interleaved gate ownership. CTA rank r computes
//   Z-cols [64r, 64r+64)          -> Z store is LOCAL (no DSMEM, no routing)
//   R-cols [256+64r, 256+64r+64)  -> every CTA broadcasts exactly 64 R*h cols
// DSMEM per CTA per step: 8KB worst-case -> 4KB, perfectly balanced.
// k-split 8, 128/64-thread reduces, f4 stores: all unchanged from R9.
// ---------------------------------------------------------------------------
extern "C" __global__ void __launch_bounds__(256, 1) __cluster_dims__(4, 1, 1)
gru_recur_il(const float* __restrict__ Uzr,
             const float* __restrict__ Uh,
             float* __restrict__ out)
{
    __shared__ float4 red4[8 * 128];   // 16 KB partials
    __shared__ float4 h4[256];         // h, rows 0..3 per hidden col
    __shared__ float4 rh4[256];        // R*h
    __shared__ float4 z4[64];          // Z for this CTA's S cols (LOCAL only)

    const int tid  = threadIdx.x;
    const int wid  = tid >> 5;        // 0..7 : k-slice [32w, 32w+32)
    const int lane = tid & 31;
    const uint32_t crank = blockIdx.x & 3;
    const int r0 = (blockIdx.x >> 2) * 4;   // first batch row of this cluster

    // ---- prologue: weight slices -> REGISTERS, h = 0 ----
    // local z-col c = 4*lane + i  (c in [0,128)):
    //   c < 64  -> global Z-col  64*crank + c
    //   c >= 64 -> global R-col  256 + 64*crank + (c - 64)
    // lane < 16 covers c in [0,64) (Z block); lane >= 16 covers R block.
    float wz[32][4];
    float wh[32][2];
    {
        const int g0 = (lane < 16) ? (int)(64 * crank + 4 * lane)
                                   : (int)(256 + 64 * crank + 4 * (lane - 16));
        const float* pz = Uzr + (size_t)(wid * 32) * 512 + g0;
        #pragma unroll
        for (int kk = 0; kk < 32; kk++)
            *(float4*)wz[kk] = *(const float4*)(pz + (size_t)kk * 512);
        const float* ph = Uh + (size_t)(wid * 32) * 256 + crank * 64 + 2 * lane;
        #pragma unroll
        for (int kk = 0; kk < 32; kk++)
            *(float2*)wh[kk] = *(const float2*)(ph + (size_t)kk * 256);
    }
    h4[tid] = make_float4(0.f, 0.f, 0.f, 0.f);
    __syncthreads();
    cluster_sync_();

    // DSMEM peer addresses (rh and h broadcast only; Z is local)
    uint32_t h_base = smem_u32(h4), rh_base = smem_u32(rh4);
    uint32_t h_r[4], rh_r[4];
    #pragma unroll
    for (uint32_t r = 0; r < 4; r++) {
        h_r[r]  = mapa_rank(h_base, r);
        rh_r[r] = mapa_rank(rh_base, r);
    }

    const ull* h_u  = (const ull*)h4;
    const ull* rh_u = (const ull*)rh4;

    #pragma unroll 1
    for (int t = 0; t < 1024; t++) {
        // ---- prefetch this step's xz / xh (DRAM; consumed at the reduces) ----
        const size_t tb = (size_t)((t << 7) + r0) * 768;
        float xz0 = 0.f, xz1 = 0.f, xz2 = 0.f, xz3 = 0.f;
        float xh0 = 0.f, xh1 = 0.f, xh2 = 0.f, xh3 = 0.f;
        if (tid < 128) {
            // interleaved: tid<64 -> Z col 64c+tid ; else R col 256+64c+(tid-64)
            int gcol = (tid < 64) ? (int)(64 * crank + tid)
                                  : (int)(256 + 64 * crank + (tid - 64));
            const float* p = g_xzh + tb + gcol;
            xz0 = p[0]; xz1 = p[768]; xz2 = p[1536]; xz3 = p[2304];
        }
        if (tid < 64) {
            const float* p = g_xzh + tb + 512 + crank * 64 + tid;
            xh0 = p[0]; xh1 = p[768]; xh2 = p[1536]; xh3 = p[2304];
        }

        // ---- phase 1: partial z[4 rows][4 cols/lane], k in [32w, 32w+32) ----
        ull a01[4] = {0, 0, 0, 0}, a23[4] = {0, 0, 0, 0};
        {
            const ull* hp = h_u + wid * 64;
            #pragma unroll
            for (int kk = 0; kk < 32; kk++) {
                ulonglong2 hv = *(const ulonglong2*)(hp + 2 * kk);  // rows (0,1),(2,3)
                ull w0 = dup2f(wz[kk][0]), w1 = dup2f(wz[kk][1]);
                ull w2 = dup2f(wz[kk][2]), w3 = dup2f(wz[kk][3]);
                ffma2(a01[0], w0, hv.x); ffma2(a23[0], w0, hv.y);
                ffma2(a01[1], w1, hv.x); ffma2(a23[1], w1, hv.y);
                ffma2(a01[2], w2, hv.x); ffma2(a23[2], w2, hv.y);
                ffma2(a01[3], w3, hv.x); ffma2(a23[3], w3, hv.y);
            }
        }
        #pragma unroll
        for (int i = 0; i < 4; i++) {
            int col = 4 * lane + i;
            int sc = col ^ ((col >> 2) & 7);                 // conflict-free swizzle
            ulonglong2 v; v.x = a01[i]; v.y = a23[i];
            *(ulonglong2*)&red4[wid * 128 + sc] = v;
        }
        __syncthreads();

        // ---- reduce1 + gates (tid < 128, local col = tid) ----
        if (tid < 128) {
            int sc = tid ^ ((tid >> 2) & 7);
            float4 s = red4[sc];
            #pragma unroll
            for (int w = 1; w < 8; w++) {
                float4 p = red4[w * 128 + sc];
                s.x += p.x; s.y += p.y; s.z += p.z; s.w += p.w;
            }
            s.x += xz0; s.y += xz1; s.z += xz2; s.w += xz3;
            float4 g;
            g.x = sigf(s.x); g.y = sigf(s.y); g.z = sigf(s.z); g.w = sigf(s.w);
            if (tid < 64) {
                // update gate Z for S col 64*crank+tid: owned locally
                z4[tid] = g;
            } else {
                // reset gate R: rh = R .* h for hidden col 64*crank + (tid-64)
                // broadcast to all 4 CTAs (4 KB per CTA, balanced)
                int ch = 64 * (int)crank + (tid - 64);
                float4 hv = h4[ch];
                float4 rh;
                rh.x = g.x * hv.x; rh.y = g.y * hv.y;
                rh.z = g.z * hv.z; rh.w = g.w * hv.w;
                uint32_t off = (uint32_t)ch * 16;
                #pragma unroll
                for (uint32_t r = 0; r < 4; r++)
                    st_cluster_f4(rh_r[r] + off, rh);
            }
        }
        cluster_sync_();

        // ---- phase 2: partial S[4 rows][2 cols/lane] ----
        ull b01[2] = {0, 0}, b23[2] = {0, 0};
        {
            const ull* rp = rh_u + wid * 64;
            #pragma unroll
            for (int kk = 0; kk < 32; kk++) {
                ulonglong2 rv = *(const ulonglong2*)(rp + 2 * kk);
                ull w0 = dup2f(wh[kk][0]), w1 = dup2f(wh[kk][1]);
                ffma2(b01[0], w0, rv.x); ffma2(b23[0], w0, rv.y);
                ffma2(b01[1], w1, rv.x); ffma2(b23[1], w1, rv.y);
            }
        }
        #pragma unroll
        for (int i = 0; i < 2; i++) {
            int col = 2 * lane + i;
            int sc = col ^ ((col >> 1) & 7);
            ulonglong2 v; v.x = b01[i]; v.y = b23[i];
            *(ulonglong2*)&red4[wid * 64 + sc] = v;
        }
        __syncthreads();

        // ---- reduce2 + combine + h broadcast (tid < 64, col = tid) ----
        if (tid < 64) {
            int sc = tid ^ ((tid >> 1) & 7);
            float4 s = red4[sc];
            #pragma unroll
            for (int w = 1; w < 8; w++) {
                float4 p = red4[w * 64 + sc];
                s.x += p.x; s.y += p.y; s.z += p.z; s.w += p.w;
            }
            float S0 = tanhfast(s.x + xh0), S1 = tanhfast(s.y + xh1);
            float S2 = tanhfast(s.z + xh2), S3 = tanhfast(s.w + xh3);
            float4 Z = z4[tid];
            int gcol = (int)crank * 64 + tid;
            float4 hv = h4[gcol];
            float4 hn;
            hn.x = fmaf(Z.x, S0 - hv.x, hv.x);
            hn.y = fmaf(Z.y, S1 - hv.y, hv.y);
            hn.z = fmaf(Z.z, S2 - hv.z, hv.z);
            hn.w = fmaf(Z.w, S3 - hv.w, hv.w);
            uint32_t off = (uint32_t)gcol * 16;
            #pragma unroll
            for (uint32_t r = 0; r < 4; r++)
                st_cluster_f4(h_r[r] + off, hn);
        }
        cluster_sync_();
    }

    // ---- epilogue: rank 0 writes the 4 rows ----
    if (crank == 0) {
        float4 hv = h4[tid];
        out[(r0 + 0) * 256 + tid] = hv.x;
        out[(r0 + 1) * 256 + tid] = hv.y;
        out[(r0 + 2) * 256 + tid] = hv.z;
        out[(r0 + 3) * 256 + tid] = hv.w;
    }
}

// ---------------------------------------------------------------------------
extern "C" void kernel_launch(void* const* d_in, const int* in_sizes, int n_in,
                              void* d_out, int out_size)
{
    (void)in_sizes; (void)n_in; (void)out_size;
    const float* x   = (const float*)d_in[0];
    const float* Wzr = (const float*)d_in[1];
    const float* Uzr = (const float*)d_in[2];
    const float* bzr = (const float*)d_in[3];
    const float* Wh  = (const float*)d_in[4];
    const float* Uh  = (const float*)d_in[5];
    const float* bh  = (const float*)d_in[6];

    dim3 ggrid(6, 1024);
    proj_gemm<<<ggrid, 256>>>(x, Wzr, Wh, bzr, bh);

    gru_recur_il<<<128, 256>>>(Uzr, Uh, (float*)d_out);
}

// round 16
// speedup vs baseline: 1.0963x; 1.0963x over previous
#include <cuda_runtime.h>
#include <math.h>
#include <stdint.h>

typedef unsigned long long ull;

// Scratch: projected inputs [t][b][768] (xz cols 0..511 incl bias, xh cols 512..767)
__device__ float g_xzh[131072 * 768];  // 402 MB static scratch

// ---------------------------------------------------------------------------
// helpers
// ---------------------------------------------------------------------------
__device__ __forceinline__ ull dup2f(float x) {
    ull r; asm("mov.b64 %0, {%1, %1};" : "=l"(r) : "f"(x)); return r;
}
__device__ __forceinline__ void unpack2(ull v, float& x, float& y) {
    asm("mov.b64 {%0, %1}, %2;" : "=f"(x), "=f"(y) : "l"(v));
}
__device__ __forceinline__ void ffma2(ull& d, ull a, ull b) {
    asm("fma.rn.f32x2 %0, %1, %2, %0;" : "+l"(d) : "l"(a), "l"(b));
}
__device__ __forceinline__ uint32_t smem_u32(const void* p) {
    return (uint32_t)__cvta_generic_to_shared(p);
}
__device__ __forceinline__ uint32_t mapa_rank(uint32_t addr, uint32_t rank) {
    uint32_t r; asm("mapa.shared::cluster.u32 %0, %1, %2;" : "=r"(r) : "r"(addr), "r"(rank));
    return r;
}
__device__ __forceinline__ void st_cluster_f4(uint32_t addr, float4 v) {
    asm volatile("st.shared::cluster.v4.f32 [%0], {%1,%2,%3,%4};"
                 :: "r"(addr), "f"(v.x), "f"(v.y), "f"(v.z), "f"(v.w) : "memory");
}
__device__ __forceinline__ void cluster_sync_() {
    asm volatile("barrier.cluster.arrive.aligned;" ::: "memory");
    asm volatile("barrier.cluster.wait.aligned;" ::: "memory");
}
__device__ __forceinline__ float sigf(float x) {
    return __fdividef(1.f, 1.f + __expf(-x));
}
__device__ __forceinline__ float tanhfast(float x) {
    float a = fabsf(x);
    float e = __expf(2.f * a);
    float r = 1.f - __fdividef(2.f, e + 1.f);
    return copysignf(r, x);
}

// ---------------------------------------------------------------------------
// Kernel 1: projection GEMM v2.  C[b*1024+t, 0:768] = x @ [Wzr|Wh] + bias.
// 256x128 tile, BK=16, 256 threads, 16x8 microtile. As stored K-MAJOR in
// smem so A row-pairs pack straight into f32x2 operands (no dup on A side).
// Per kk: 4+2 LDS.128 + 8 dup + 64 FFMA2 -> 82% FFMA2 issue density.
// ---------------------------------------------------------------------------
__global__ __launch_bounds__(256, 1) void proj_gemm(
    const float* __restrict__ x,
    const float* __restrict__ Wzr,
    const float* __restrict__ Wh,
    const float* __restrict__ bzr,
    const float* __restrict__ bh)
{
    __shared__ float As[2][16][256];   // k-major: As[buf][k][m], 32 KB
    __shared__ float Bs[2][16][128];   // 16 KB

    const int tid = threadIdx.x;
    const int tm = tid >> 4;          // 0..15 -> rows tm*16..+16
    const int tn = tid & 15;          // 0..15 -> cols tn*8..+8
    const int Mbase = blockIdx.y * 256;
    const int Nbase = blockIdx.x * 128;

    const bool isZr = (Nbase < 512);
    const float* __restrict__ W = isZr ? Wzr : Wh;
    const int ldw  = isZr ? 512 : 256;
    const int wcol = isZr ? Nbase : (Nbase - 512);

    ull acc2[8][8];                    // [row-pair][col], f32x2 over rows
    #pragma unroll
    for (int rp = 0; rp < 8; rp++)
        #pragma unroll
        for (int j = 0; j < 8; j++) acc2[rp][j] = 0ull;

    const int ra = tid >> 2;          // 0..63 (rows ra + 64q)
    const int ka = (tid & 3) << 2;    // k 0,4,8,12
    const int rb = tid >> 5;          // 0..7
    const int nb = (tid & 31) << 2;   // 0..124

    float4 a[4];
    float4 w0, w1;

    // preload tile 0
    #pragma unroll
    for (int q = 0; q < 4; q++)
        a[q] = *(const float4*)&x[(size_t)(Mbase + ra + 64 * q) * 256 + ka];
    w0 = *(const float4*)&W[(size_t)(rb)     * ldw + wcol + nb];
    w1 = *(const float4*)&W[(size_t)(rb + 8) * ldw + wcol + nb];
    #pragma unroll
    for (int q = 0; q < 4; q++) {
        As[0][ka + 0][ra + 64 * q] = a[q].x;
        As[0][ka + 1][ra + 64 * q] = a[q].y;
        As[0][ka + 2][ra + 64 * q] = a[q].z;
        As[0][ka + 3][ra + 64 * q] = a[q].w;
    }
    *(float4*)&Bs[0][rb][nb]     = w0;
    *(float4*)&Bs[0][rb + 8][nb] = w1;
    __syncthreads();

    int cur = 0;
    for (int kt = 16; kt <= 256; kt += 16) {
        if (kt < 256) {
            #pragma unroll
            for (int q = 0; q < 4; q++)
                a[q] = *(const float4*)&x[(size_t)(Mbase + ra + 64 * q) * 256 + kt + ka];
            w0 = *(const float4*)&W[(size_t)(kt + rb)     * ldw + wcol + nb];
            w1 = *(const float4*)&W[(size_t)(kt + rb + 8) * ldw + wcol + nb];
        }
        #pragma unroll
        for (int kk = 0; kk < 16; kk++) {
            // A: 16 consecutive rows -> 8 packed row-pairs (no dup needed)
            ulonglong2 A01 = *(const ulonglong2*)&As[cur][kk][tm * 16];
            ulonglong2 A23 = *(const ulonglong2*)&As[cur][kk][tm * 16 + 4];
            ulonglong2 A45 = *(const ulonglong2*)&As[cur][kk][tm * 16 + 8];
            ulonglong2 A67 = *(const ulonglong2*)&As[cur][kk][tm * 16 + 12];
            ull Ar[8] = {A01.x, A01.y, A23.x, A23.y, A45.x, A45.y, A67.x, A67.y};
            float4 bv0 = *(const float4*)&Bs[cur][kk][tn * 8];
            float4 bv1 = *(const float4*)&Bs[cur][kk][tn * 8 + 4];
            ull bd[8];
            bd[0] = dup2f(bv0.x); bd[1] = dup2f(bv0.y);
            bd[2] = dup2f(bv0.z); bd[3] = dup2f(bv0.w);
            bd[4] = dup2f(bv1.x); bd[5] = dup2f(bv1.y);
            bd[6] = dup2f(bv1.z); bd[7] = dup2f(bv1.w);
            #pragma unroll
            for (int j = 0; j < 8; j++)
                #pragma unroll
                for (int rp = 0; rp < 8; rp++)
                    ffma2(acc2[rp][j], Ar[rp], bd[j]);
        }
        if (kt < 256) {
            int nxt = cur ^ 1;
            #pragma unroll
            for (int q = 0; q < 4; q++) {
                As[nxt][ka + 0][ra + 64 * q] = a[q].x;
                As[nxt][ka + 1][ra + 64 * q] = a[q].y;
                As[nxt][ka + 2][ra + 64 * q] = a[q].z;
                As[nxt][ka + 3][ra + 64 * q] = a[q].w;
            }
            *(float4*)&Bs[nxt][rb][nb]     = w0;
            *(float4*)&Bs[nxt][rb + 8][nb] = w1;
            __syncthreads();
            cur = nxt;
        }
    }

    // bias folded here so the recurrence never touches it
    float bias[8];
    #pragma unroll
    for (int jj = 0; jj < 8; jj++) {
        int c = Nbase + tn * 8 + jj;
        bias[jj] = (c < 512) ? bzr[c] : bh[c - 512];
    }

    #pragma unroll
    for (int rp = 0; rp < 8; rp++) {
        float c0[8], c1[8];
        #pragma unroll
        for (int j = 0; j < 8; j++) unpack2(acc2[rp][j], c0[j], c1[j]);
        #pragma unroll
        for (int half = 0; half < 2; half++) {
            const float* c = half ? c1 : c0;
            int r = Mbase + tm * 16 + 2 * rp + half;   // r = b*1024 + t
            int b = r >> 10;
            int t = r & 1023;
            float* dst = &g_xzh[(size_t)((t << 7) + b) * 768 + Nbase + tn * 8];
            float4 v0, v1;
            v0.x = c[0] + bias[0]; v0.y = c[1] + bias[1];
            v0.z = c[2] + bias[2]; v0.w = c[3] + bias[3];
            v1.x = c[4] + bias[4]; v1.y = c[5] + bias[5];
            v1.z = c[6] + bias[6]; v1.w = c[7] + bias[7];
            *(float4*)dst       = v0;
            *(float4*)(dst + 4) = v1;
        }
    }
}

// ---------------------------------------------------------------------------
// Kernel 2: GRU recurrence — EXACT R9 kernel (best measured: 2437 us).
// 32 clusters x 4 CTAs x 256 threads, register-resident weights,
// cluster.sync. No changes.
// ---------------------------------------------------------------------------
extern "C" __global__ void __launch_bounds__(256, 1) __cluster_dims__(4, 1, 1)
gru_recur_reg(const float* __restrict__ Uzr,
              const float* __restrict__ Uh,
              float* __restrict__ out)
{
    __shared__ float4 red4[8 * 128];   // 16 KB partials
    __shared__ float4 h4[256];         // h, rows 0..3 per hidden col
    __shared__ float4 rh4[256];        // R*h
    __shared__ float4 z4[64];          // Z slice for this CTA's S cols

    const int tid  = threadIdx.x;
    const int wid  = tid >> 5;        // 0..7 : k-slice [32w, 32w+32)
    const int lane = tid & 31;
    const uint32_t crank = blockIdx.x & 3;
    const int r0 = (blockIdx.x >> 2) * 4;   // first batch row of this cluster

    // ---- prologue: weight slices -> REGISTERS, h = 0 ----
    float wz[32][4];
    float wh[32][2];
    {
        const float* pz = Uzr + (size_t)(wid * 32) * 512 + crank * 128 + 4 * lane;
        #pragma unroll
        for (int kk = 0; kk < 32; kk++)
            *(float4*)wz[kk] = *(const float4*)(pz + (size_t)kk * 512);
        const float* ph = Uh + (size_t)(wid * 32) * 256 + crank * 64 + 2 * lane;
        #pragma unroll
        for (int kk = 0; kk < 32; kk++)
            *(float2*)wh[kk] = *(const float2*)(ph + (size_t)kk * 256);
    }
    h4[tid] = make_float4(0.f, 0.f, 0.f, 0.f);
    __syncthreads();
    cluster_sync_();

    // DSMEM peer addresses
    uint32_t h_base = smem_u32(h4), rh_base = smem_u32(rh4), z_base = smem_u32(z4);
    uint32_t h_r[4], rh_r[4], z_r[4];
    #pragma unroll
    for (uint32_t r = 0; r < 4; r++) {
        h_r[r]  = mapa_rank(h_base, r);
        rh_r[r] = mapa_rank(rh_base, r);
        z_r[r]  = mapa_rank(z_base, r);
    }

    const ull* h_u  = (const ull*)h4;
    const ull* rh_u = (const ull*)rh4;

    #pragma unroll 1
    for (int t = 0; t < 1024; t++) {
        // ---- prefetch this step's xz / xh (DRAM; consumed at the reduces) ----
        const size_t tb = (size_t)((t << 7) + r0) * 768;
        float xz0 = 0.f, xz1 = 0.f, xz2 = 0.f, xz3 = 0.f;
        float xh0 = 0.f, xh1 = 0.f, xh2 = 0.f, xh3 = 0.f;
        if (tid < 128) {
            const float* p = g_xzh + tb + crank * 128 + tid;
            xz0 = p[0]; xz1 = p[768]; xz2 = p[1536]; xz3 = p[2304];
        }
        if (tid < 64) {
            const float* p = g_xzh + tb + 512 + crank * 64 + tid;
            xh0 = p[0]; xh1 = p[768]; xh2 = p[1536]; xh3 = p[2304];
        }

        // ---- phase 1: partial z[4 rows][4 cols/lane], k in [32w, 32w+32) ----
        ull a01[4] = {0, 0, 0, 0}, a23[4] = {0, 0, 0, 0};
        {
            const ull* hp = h_u + wid * 64;
            #pragma unroll
            for (int kk = 0; kk < 32; kk++) {
                ulonglong2 hv = *(const ulonglong2*)(hp + 2 * kk);  // rows (0,1),(2,3)
                ull w0 = dup2f(wz[kk][0]), w1 = dup2f(wz[kk][1]);
                ull w2 = dup2f(wz[kk][2]), w3 = dup2f(wz[kk][3]);
                ffma2(a01[0], w0, hv.x); ffma2(a23[0], w0, hv.y);
                ffma2(a01[1], w1, hv.x); ffma2(a23[1], w1, hv.y);
                ffma2(a01[2], w2, hv.x); ffma2(a23[2], w2, hv.y);
                ffma2(a01[3], w3, hv.x); ffma2(a23[3], w3, hv.y);
            }
        }
        #pragma unroll
        for (int i = 0; i < 4; i++) {
            int col = 4 * lane + i;
            int sc = col ^ ((col >> 2) & 7);                 // conflict-free swizzle
            ulonglong2 v; v.x = a01[i]; v.y = a23[i];
            *(ulonglong2*)&red4[wid * 128 + sc] = v;
        }
        __syncthreads();

        // ---- reduce1 + gates + DSMEM routing (tid < 128, col = tid) ----
        if (tid < 128) {
            int sc = tid ^ ((tid >> 2) & 7);
            float4 s = red4[sc];
            #pragma unroll
            for (int w = 1; w < 8; w++) {
                float4 p = red4[w * 128 + sc];
                s.x += p.x; s.y += p.y; s.z += p.z; s.w += p.w;
            }
            s.x += xz0; s.y += xz1; s.z += xz2; s.w += xz3;
            float4 g;
            g.x = sigf(s.x); g.y = sigf(s.y); g.z = sigf(s.z); g.w = sigf(s.w);
            if (crank < 2) {
                // update gate Z: route to the CTA owning these S columns
                uint32_t dest = 2 * crank + (uint32_t)(tid >> 6);
                st_cluster_f4(z_r[dest] + (uint32_t)(tid & 63) * 16, g);
            } else {
                // reset gate R: rh = R .* h, broadcast to all 4 CTAs
                int ch = ((int)crank - 2) * 128 + tid;       // hidden col
                float4 hv = h4[ch];
                float4 rh;
                rh.x = g.x * hv.x; rh.y = g.y * hv.y;
                rh.z = g.z * hv.z; rh.w = g.w * hv.w;
                uint32_t off = (uint32_t)ch * 16;
                #pragma unroll
                for (uint32_t r = 0; r < 4; r++)
                    st_cluster_f4(rh_r[r] + off, rh);
            }
        }
        cluster_sync_();

        // ---- phase 2: partial S[4 rows][2 cols/lane] ----
        ull b01[2] = {0, 0}, b23[2] = {0, 0};
        {
            const ull* rp = rh_u + wid * 64;
            #pragma unroll
            for (int kk = 0; kk < 32; kk++) {
                ulonglong2 rv = *(const ulonglong2*)(rp + 2 * kk);
                ull w0 = dup2f(wh[kk][0]), w1 = dup2f(wh[kk][1]);
                ffma2(b01[0], w0, rv.x); ffma2(b23[0], w0, rv.y);
                ffma2(b01[1], w1, rv.x); ffma2(b23[1], w1, rv.y);
            }
        }
        #pragma unroll
        for (int i = 0; i < 2; i++) {
            int col = 2 * lane + i;
            int sc = col ^ ((col >> 1) & 7);
            ulonglong2 v; v.x = b01[i]; v.y = b23[i];
            *(ulonglong2*)&red4[wid * 64 + sc] = v;
        }
        __syncthreads();

        // ---- reduce2 + combine + h broadcast (tid < 64, col = tid) ----
        if (tid < 64) {
            int sc = tid ^ ((tid >> 1) & 7);
            float4 s = red4[sc];
            #pragma unroll
            for (int w = 1; w < 8; w++) {
                float4 p = red4[w * 64 + sc];
                s.x += p.x; s.y += p.y; s.z += p.z; s.w += p.w;
            }
            float S0 = tanhfast(s.x + xh0), S1 = tanhfast(s.y + xh1);
            float S2 = tanhfast(s.z + xh2), S3 = tanhfast(s.w + xh3);
            float4 Z = z4[tid];
            int gcol = (int)crank * 64 + tid;
            float4 hv = h4[gcol];
            float4 hn;
            hn.x = fmaf(Z.x, S0 - hv.x, hv.x);
            hn.y = fmaf(Z.y, S1 - hv.y, hv.y);
            hn.z = fmaf(Z.z, S2 - hv.z, hv.z);
            hn.w = fmaf(Z.w, S3 - hv.w, hv.w);
            uint32_t off = (uint32_t)gcol * 16;
            #pragma unroll
            for (uint32_t r = 0; r < 4; r++)
                st_cluster_f4(h_r[r] + off, hn);
        }
        cluster_sync_();
    }

    // ---- epilogue: rank 0 writes the 4 rows ----
    if (crank == 0) {
        float4 hv = h4[tid];
        out[(r0 + 0) * 256 + tid] = hv.x;
        out[(r0 + 1) * 256 + tid] = hv.y;
        out[(r0 + 2) * 256 + tid] = hv.z;
        out[(r0 + 3) * 256 + tid] = hv.w;
    }
}

// ---------------------------------------------------------------------------
extern "C" void kernel_launch(void* const* d_in, const int* in_sizes, int n_in,
                              void* d_out, int out_size)
{
    (void)in_sizes; (void)n_in; (void)out_size;
    const float* x   = (const float*)d_in[0];
    const float* Wzr = (const float*)d_in[1];
    const float* Uzr = (const float*)d_in[2];
    const float* bzr = (const float*)d_in[3];
    const float* Wh  = (const float*)d_in[4];
    const float* Uh  = (const float*)d_in[5];
    const float* bh  = (const float*)d_in[6];

    dim3 ggrid(6, 512);                    // 768/128 x 131072/256
    proj_gemm<<<ggrid, 256>>>(x, Wzr, Wh, bzr, bh);

    gru_recur_reg<<<128, 256>>>(Uzr, Uh, (float*)d_out);
}